// round 8
// baseline (speedup 1.0000x reference)
#include <cuda_runtime.h>
#include <cuda_bf16.h>
#include <math.h>
#include <stdint.h>

#define B_  8
#define N_  4096
#define D_  1024
#define H_  16
#define DH_ 64
#define M_  (B_ * N_)   // 32768 rows

// ---------------- scratch (static device memory; allocation-free) ----------
__device__ __nv_bfloat16 g_Whi[(size_t)3 * D_ * D_];    // split Wq|Wk|Wv
__device__ __nv_bfloat16 g_Wlo[(size_t)3 * D_ * D_];
__device__ float g_Q[(size_t)M_ * D_];                  // post-elu Q (fp32)
__device__ float g_K[(size_t)M_ * D_];
__device__ float g_V[(size_t)M_ * D_];
__device__ __nv_bfloat16 g_GThi[(size_t)B_ * D_ * D_];  // folded Wo∘kv∘qnorm, split
__device__ __nv_bfloat16 g_GTlo[(size_t)B_ * D_ * D_];
__device__ float g_qnorm[B_ * D_];
__device__ float g_kv[B_ * H_ * DH_ * DH_];

// =====================  helpers  ===========================================
__device__ __forceinline__ uint32_t smem_addr_u32(const void* p) {
    uint32_t a;
    asm("{ .reg .u64 t; cvta.to.shared.u64 t, %1; cvt.u32.u64 %0, t; }"
        : "=r"(a) : "l"(p));
    return a;
}

// fp32 pair -> packed bf16x2 hi and lo (x in low half)
__device__ __forceinline__ void split_pack(float x, float y, uint32_t& hi, uint32_t& lo) {
    __nv_bfloat162 h = __floats2bfloat162_rn(x, y);
    float hx = __bfloat162float(__low2bfloat16(h));
    float hy = __bfloat162float(__high2bfloat16(h));
    __nv_bfloat162 l = __floats2bfloat162_rn(x - hx, y - hy);
    hi = *reinterpret_cast<uint32_t*>(&h);
    lo = *reinterpret_cast<uint32_t*>(&l);
}

__device__ __forceinline__ void sts_b64(uint32_t a, uint32_t x, uint32_t y) {
    asm volatile("st.shared.v2.b32 [%0], {%1, %2};" :: "r"(a), "r"(x), "r"(y) : "memory");
}

__device__ __forceinline__ void mma16816(float* c, const uint32_t* a, const uint32_t* b) {
    asm volatile(
        "mma.sync.aligned.m16n8k16.row.col.f32.bf16.bf16.f32 "
        "{%0,%1,%2,%3}, {%4,%5,%6,%7}, {%8,%9}, {%0,%1,%2,%3};"
        : "+f"(c[0]), "+f"(c[1]), "+f"(c[2]), "+f"(c[3])
        : "r"(a[0]), "r"(a[1]), "r"(a[2]), "r"(a[3]), "r"(b[0]), "r"(b[1]));
}

#define LDSM4(r, a)                                                            \
    asm volatile("ldmatrix.sync.aligned.m8n8.x4.shared.b16 {%0,%1,%2,%3}, [%4];" \
        : "=r"((r)[0]), "=r"((r)[1]), "=r"((r)[2]), "=r"((r)[3]) : "r"(a))

#define CP_ASYNC16(dst, src)                                                   \
    asm volatile("cp.async.cg.shared.global [%0], [%1], 16;"                   \
        :: "r"(dst), "l"(src) : "memory")
#define CP_COMMIT()  asm volatile("cp.async.commit_group;" ::: "memory")
#define CP_WAIT1()   asm volatile("cp.async.wait_group 1;" ::: "memory")

// ---------------------------------------------------------------------------
// smem: A 2-stage (hi +0, lo +10240, stride 20480); B 3-stage at +40960.
// ---------------------------------------------------------------------------
#define ASTG_ 20480u
#define BBASE_ 40960u
#define BSTG_ 20480u
static constexpr size_t GEMM_SMEM = 102400;

// ---------------------------------------------------------------------------
// Shared mainloop: acc += A_fp32 @ (Bhi+Blo)^T over K=1024.
// Manual schedule (asm volatile preserves order): B frags double-buffered
// across ng; MMAs product-major (RAW distance 4 per accumulator).
// ---------------------------------------------------------------------------
__device__ __forceinline__ void gemm_mainloop(
    const float* Ap, const __nv_bfloat16* Bp,
    uint32_t sb, uint32_t a_sts, uint32_t b_dst,
    uint32_t a_off, uint32_t b_off, float acc[2][8][4])
{
    float4 pa[4];

    // ---- prologue: B(0), B(1) in flight; A(0)->smem buf0; A(1)->regs ----
#pragma unroll
    for (int st = 0; st < 2; st++) {
        const uint32_t bd = b_dst + (uint32_t)st * BSTG_;
        const __nv_bfloat16* g0 = Bp + st * 32;
#pragma unroll
        for (int c = 0; c < 4; c++)
            CP_ASYNC16(bd + c * 16u, g0 + c * 8);
        CP_COMMIT();
    }
#pragma unroll
    for (int i = 0; i < 4; i++)
        pa[i] = *(const float4*)(Ap + (size_t)(i << 5) * D_);
#pragma unroll
    for (int i = 0; i < 4; i++) {
        uint32_t h01, l01, h23, l23;
        split_pack(pa[i].x, pa[i].y, h01, l01);
        split_pack(pa[i].z, pa[i].w, h23, l23);
        const uint32_t o = a_sts + (uint32_t)(i * 32 * 80);
        sts_b64(o, h01, h23);
        sts_b64(o + 10240u, l01, l23);
    }
#pragma unroll
    for (int i = 0; i < 4; i++)
        pa[i] = *(const float4*)(Ap + 32 + (size_t)(i << 5) * D_);

    int bs = 0;   // s % 3
#pragma unroll 1
    for (int s = 0; s < 32; s++) {
        CP_WAIT1();
        __syncthreads();

        if (s < 31) {
            const uint32_t an = a_sts + (uint32_t)((s + 1) & 1) * ASTG_;
#pragma unroll
            for (int i = 0; i < 4; i++) {
                uint32_t h01, l01, h23, l23;
                split_pack(pa[i].x, pa[i].y, h01, l01);
                split_pack(pa[i].z, pa[i].w, h23, l23);
                const uint32_t o = an + (uint32_t)(i * 32 * 80);
                sts_b64(o, h01, h23);
                sts_b64(o + 10240u, l01, l23);
            }
        }
        if (s + 2 < 32) {
            const int k0n = (s + 2) << 5;
#pragma unroll
            for (int i = 0; i < 4; i++)
                pa[i] = *(const float4*)(Ap + k0n + (size_t)(i << 5) * D_);
            const int bs2 = (bs + 2 >= 3) ? bs - 1 : bs + 2;
            const uint32_t bd = b_dst + (uint32_t)bs2 * BSTG_;
#pragma unroll
            for (int c = 0; c < 4; c++)
                CP_ASYNC16(bd + c * 16u, Bp + k0n + c * 8);
        }
        CP_COMMIT();

        const uint32_t ca = sb + (uint32_t)(s & 1) * ASTG_;
        const uint32_t cb = sb + BBASE_ + (uint32_t)bs * BSTG_;
#pragma unroll
        for (int kk = 0; kk < 2; kk++) {
            const uint32_t ko = (uint32_t)kk * 32u;
            uint32_t ah[2][4], al[2][4];
            uint32_t bh[2][4], bl[2][4];     // ng double buffer
            LDSM4(ah[0], ca + a_off + ko);
            LDSM4(al[0], ca + 10240u + a_off + ko);
            LDSM4(ah[1], ca + a_off + 1280u + ko);
            LDSM4(al[1], ca + 10240u + a_off + 1280u + ko);
            LDSM4(bh[0], cb + b_off + ko);
            LDSM4(bl[0], cb + 10240u + b_off + ko);
#pragma unroll
            for (int ng = 0; ng < 4; ng++) {
                const int cur = ng & 1, nxt = cur ^ 1;
                if (ng < 3) {
                    LDSM4(bh[nxt], cb + b_off + (uint32_t)(ng + 1) * 1280u + ko);
                    LDSM4(bl[nxt], cb + 10240u + b_off + (uint32_t)(ng + 1) * 1280u + ko);
                }
                float* a00 = acc[0][2 * ng];
                float* a01 = acc[0][2 * ng + 1];
                float* a10 = acc[1][2 * ng];
                float* a11 = acc[1][2 * ng + 1];
                mma16816(a00, ah[0], bh[cur]);
                mma16816(a01, ah[0], bh[cur] + 2);
                mma16816(a10, ah[1], bh[cur]);
                mma16816(a11, ah[1], bh[cur] + 2);
                mma16816(a00, ah[0], bl[cur]);
                mma16816(a01, ah[0], bl[cur] + 2);
                mma16816(a10, ah[1], bl[cur]);
                mma16816(a11, ah[1], bl[cur] + 2);
                mma16816(a00, al[0], bh[cur]);
                mma16816(a01, al[0], bh[cur] + 2);
                mma16816(a10, al[1], bh[cur]);
                mma16816(a11, al[1], bh[cur] + 2);
            }
        }
        bs = (bs + 1 >= 3) ? 0 : bs + 1;
    }
}

// ---------------------------------------------------------------------------
// Fused Q/K/V projection GEMM; z = blockIdx.z selects input/weights/epilogue.
// ---------------------------------------------------------------------------
__global__ void __launch_bounds__(256, 2)
gemm_qkv(const float* __restrict__ Aq, const float* __restrict__ Ak,
         const float* __restrict__ Av,
         const float* __restrict__ bq, const float* __restrict__ bk,
         const float* __restrict__ bv, const int* __restrict__ mask)
{
    extern __shared__ __align__(16) char smem[];
    const uint32_t sb = smem_addr_u32(smem);
    const int tid  = threadIdx.x;
    const int lane = tid & 31;
    const int wid  = tid >> 5;
    const int warpM = wid & 3;
    const int warpN = wid >> 2;
    const int bm = blockIdx.y << 7;
    const int bn = blockIdx.x << 7;
    const int z  = blockIdx.z;

    const float* A    = (z == 0) ? Aq : (z == 1) ? Ak : Av;
    const float* bias = (z == 0) ? bq : (z == 1) ? bk : bv;
    float* C          = (z == 0) ? g_Q : (z == 1) ? g_K : g_V;
    const size_t wofs = (size_t)z << 20;
    const __nv_bfloat16* Bhi = g_Whi + wofs;
    const __nv_bfloat16* Blo = g_Wlo + wofs;

    const int r0 = tid >> 3;
    const int c4 = tid & 7;
    const float* Ap = A + (size_t)(bm + r0) * D_ + (c4 << 2);
    const uint32_t a_sts = sb + (uint32_t)(r0 * 80 + c4 * 8);

    const int barr = tid >> 7;
    const int brow = tid & 127;
    const __nv_bfloat16* Bp = (barr ? Blo : Bhi) + (size_t)(bn + brow) * D_;
    const uint32_t b_dst = sb + BBASE_ + (barr ? 10240u : 0u) + (uint32_t)brow * 80u;

    const uint32_t a_off = (uint32_t)(((lane & 7) + ((lane >> 3) & 1) * 8 + warpM * 32) * 80
                                      + ((lane >> 4) & 1) * 16);
    const uint32_t b_off = (uint32_t)(((lane & 7) + ((lane >> 4) & 1) * 8 + warpN * 64) * 80
                                      + ((lane >> 3) & 1) * 16);

    float acc[2][8][4];
#pragma unroll
    for (int mt = 0; mt < 2; mt++)
#pragma unroll
        for (int nt = 0; nt < 8; nt++)
#pragma unroll
            for (int r = 0; r < 4; r++) acc[mt][nt][r] = 0.f;

    gemm_mainloop(Ap, Bp, sb, a_sts, b_dst, a_off, b_off, acc);

    const bool do_elu  = (z != 2);
    const bool do_mask = (z == 1);
    const int g = lane >> 2, t = lane & 3;
#pragma unroll
    for (int mt = 0; mt < 2; mt++) {
        const int row0 = bm + warpM * 32 + mt * 16 + g;
        const int row1 = row0 + 8;
        int m0 = 0, m1 = 0;
        if (do_mask) { m0 = mask[row0]; m1 = mask[row1]; }
#pragma unroll
        for (int nt = 0; nt < 8; nt++) {
            const int col = bn + warpN * 64 + nt * 8 + t * 2;
            const float2 bv2 = *(const float2*)(bias + col);
            float v0 = acc[mt][nt][0] + bv2.x;
            float v1 = acc[mt][nt][1] + bv2.y;
            float v2 = acc[mt][nt][2] + bv2.x;
            float v3 = acc[mt][nt][3] + bv2.y;
            if (do_elu) {
                v0 = (v0 > 0.f) ? (v0 + 1.f) : expf(v0);
                v1 = (v1 > 0.f) ? (v1 + 1.f) : expf(v1);
                v2 = (v2 > 0.f) ? (v2 + 1.f) : expf(v2);
                v3 = (v3 > 0.f) ? (v3 + 1.f) : expf(v3);
            }
            if (do_mask) {
                if (m0) { v0 = 0.f; v1 = 0.f; }
                if (m1) { v2 = 0.f; v3 = 0.f; }
            }
            *(float2*)(C + (size_t)row0 * D_ + col) = make_float2(v0, v1);
            *(float2*)(C + (size_t)row1 * D_ + col) = make_float2(v2, v3);
        }
    }
}

// ---------------------------------------------------------------------------
// Output GEMM: out = Q @ GT_b^T + bo  (B per-batch: + (bm>>12)*1M)
// ---------------------------------------------------------------------------
__global__ void __launch_bounds__(256, 2)
gemm_out(const float* __restrict__ A, const float* __restrict__ bias,
         float* __restrict__ C)
{
    extern __shared__ __align__(16) char smem[];
    const uint32_t sb = smem_addr_u32(smem);
    const int tid  = threadIdx.x;
    const int lane = tid & 31;
    const int wid  = tid >> 5;
    const int warpM = wid & 3;
    const int warpN = wid >> 2;
    const int bm = blockIdx.y << 7;
    const int bn = blockIdx.x << 7;

    const size_t ofs = ((size_t)(bm >> 12)) << 20;
    const __nv_bfloat16* Bhi = g_GThi + ofs;
    const __nv_bfloat16* Blo = g_GTlo + ofs;

    const int r0 = tid >> 3;
    const int c4 = tid & 7;
    const float* Ap = A + (size_t)(bm + r0) * D_ + (c4 << 2);
    const uint32_t a_sts = sb + (uint32_t)(r0 * 80 + c4 * 8);

    const int barr = tid >> 7;
    const int brow = tid & 127;
    const __nv_bfloat16* Bp = (barr ? Blo : Bhi) + (size_t)(bn + brow) * D_;
    const uint32_t b_dst = sb + BBASE_ + (barr ? 10240u : 0u) + (uint32_t)brow * 80u;

    const uint32_t a_off = (uint32_t)(((lane & 7) + ((lane >> 3) & 1) * 8 + warpM * 32) * 80
                                      + ((lane >> 4) & 1) * 16);
    const uint32_t b_off = (uint32_t)(((lane & 7) + ((lane >> 4) & 1) * 8 + warpN * 64) * 80
                                      + ((lane >> 3) & 1) * 16);

    float acc[2][8][4];
#pragma unroll
    for (int mt = 0; mt < 2; mt++)
#pragma unroll
        for (int nt = 0; nt < 8; nt++)
#pragma unroll
            for (int r = 0; r < 4; r++) acc[mt][nt][r] = 0.f;

    gemm_mainloop(Ap, Bp, sb, a_sts, b_dst, a_off, b_off, acc);

    const int g = lane >> 2, t = lane & 3;
#pragma unroll
    for (int mt = 0; mt < 2; mt++) {
        const int row0 = bm + warpM * 32 + mt * 16 + g;
        const int row1 = row0 + 8;
#pragma unroll
        for (int nt = 0; nt < 8; nt++) {
            const int col = bn + warpN * 64 + nt * 8 + t * 2;
            const float2 bv2 = *(const float2*)(bias + col);
            *(float2*)(C + (size_t)row0 * D_ + col) =
                make_float2(acc[mt][nt][0] + bv2.x, acc[mt][nt][1] + bv2.y);
            *(float2*)(C + (size_t)row1 * D_ + col) =
                make_float2(acc[mt][nt][2] + bv2.x, acc[mt][nt][3] + bv2.y);
        }
    }
}

// ---------------------------------------------------------------------------
// weight pre-split (tiny: 3 x 1M elements)
// ---------------------------------------------------------------------------
__global__ void __launch_bounds__(256) split_w_kernel(
    const float* __restrict__ w0, const float* __restrict__ w1,
    const float* __restrict__ w2)
{
    const float* src = (blockIdx.y == 0) ? w0 : (blockIdx.y == 1) ? w1 : w2;
    const size_t i4 = (size_t)blockIdx.x * 256 + threadIdx.x;
    float4 v = ((const float4*)src)[i4];
    uint32_t h01, l01, h23, l23;
    split_pack(v.x, v.y, h01, l01);
    split_pack(v.z, v.w, h23, l23);
    const size_t o = ((size_t)blockIdx.y << 20) + i4 * 4;
    *(uint2*)(g_Whi + o) = make_uint2(h01, h23);
    *(uint2*)(g_Wlo + o) = make_uint2(l01, l23);
}

__global__ void zero_qnorm_kernel()
{
    const int i = blockIdx.x * 256 + threadIdx.x;
    if (i < B_ * D_) g_qnorm[i] = 0.f;
}

__global__ void zero_kv_kernel()
{
    const int i = blockIdx.x * 256 + threadIdx.x;
    if (i < B_ * H_ * DH_ * DH_) g_kv[i] = 0.f;
}

// ---------------------------------------------------------------------------
// q column sum-of-squares over sequence axis (atomics)
// ---------------------------------------------------------------------------
__global__ void __launch_bounds__(256) qcolsumsq_kernel()
{
    const int c  = blockIdx.x * 256 + threadIdx.x;
    const int b  = blockIdx.z;
    const int n0 = blockIdx.y * 256;
    const float* p = g_Q + ((size_t)(b * N_ + n0)) * D_ + c;
    float s = 0.f;
#pragma unroll 8
    for (int j = 0; j < 256; j++) {
        const float v = p[(size_t)j * D_];
        s = fmaf(v, v, s);
    }
    atomicAdd(&g_qnorm[b * D_ + c], s);
}

// ---------------------------------------------------------------------------
// fused knorm + kv: kv[b,h,d,e] += sum_n knorm(k)[.,d] * v[.,e]
// ---------------------------------------------------------------------------
__global__ void __launch_bounds__(256) kv_fused_kernel()
{
    __shared__ __align__(16) float Ks[64][64];
    __shared__ __align__(16) float Vs[64][64];
    const int tid = threadIdx.x;
    const int bh  = blockIdx.x;
    const int b   = bh >> 4, h = bh & 15;
    const int n0  = blockIdx.y << 9;
    const size_t base = (size_t)b * N_ * D_ + (size_t)h * DH_;
    const int d0 = (tid & 15) << 2;
    const int e0 = (tid >> 4) << 2;

    float acc[4][4];
#pragma unroll
    for (int i = 0; i < 4; i++)
#pragma unroll
        for (int j = 0; j < 4; j++) acc[i][j] = 0.f;

    for (int tile = 0; tile < 512; tile += 64) {
        __syncthreads();
#pragma unroll
        for (int it = 0; it < 4; it++) {
            const int rj = (it << 4) + (tid >> 4);
            const int q  = (tid & 15) << 2;
            const size_t gi = base + (size_t)(n0 + tile + rj) * D_ + q;
            float4 kd = *(const float4*)(g_K + gi);
            float s = kd.x * kd.x + kd.y * kd.y + kd.z * kd.z + kd.w * kd.w;
            s += __shfl_xor_sync(0xffffffffu, s, 1);
            s += __shfl_xor_sync(0xffffffffu, s, 2);
            s += __shfl_xor_sync(0xffffffffu, s, 4);
            s += __shfl_xor_sync(0xffffffffu, s, 8);
            const float inv = 1.0f / fmaxf(sqrtf(s), 1e-12f);
            kd.x *= inv; kd.y *= inv; kd.z *= inv; kd.w *= inv;
            *(float4*)&Ks[rj][q] = kd;
            *(float4*)&Vs[rj][q] = *(const float4*)(g_V + gi);
        }
        __syncthreads();
#pragma unroll 8
        for (int j = 0; j < 64; j++) {
            const float4 kd = *(const float4*)&Ks[j][d0];
            const float4 ve = *(const float4*)&Vs[j][e0];
            const float kda[4] = {kd.x, kd.y, kd.z, kd.w};
            const float vea[4] = {ve.x, ve.y, ve.z, ve.w};
#pragma unroll
            for (int di = 0; di < 4; di++)
#pragma unroll
                for (int ei = 0; ei < 4; ei++)
                    acc[di][ei] = fmaf(kda[di], vea[ei], acc[di][ei]);
        }
    }

    float* outp = g_kv + (size_t)bh * (DH_ * DH_);
#pragma unroll
    for (int di = 0; di < 4; di++)
#pragma unroll
        for (int ei = 0; ei < 4; ei++)
            atomicAdd(&outp[(d0 + di) * DH_ + e0 + ei], acc[di][ei]);
}

// ---------------------------------------------------------------------------
// GT_b[j][h*64+d] = (sum_e kv[b,h][d][e] * Wo[j][h*64+e]) / max(sqrt(qn),eps)
// ---------------------------------------------------------------------------
__global__ void __launch_bounds__(256) gt_kernel(const float* __restrict__ Wo)
{
    __shared__ __align__(16) float kvs[64][65];
    __shared__ __align__(16) float Wos[64][65];
    const int tid = threadIdx.x;
    const int jt = blockIdx.x, h = blockIdx.y, b = blockIdx.z;
    const float* kvp = g_kv + (size_t)(b * H_ + h) * (DH_ * DH_);

#pragma unroll
    for (int i = 0; i < 16; i++) {
        const int idx = tid + (i << 8);
        const int r = idx >> 6, e = idx & 63;
        kvs[r][e] = kvp[idx];
        Wos[r][e] = Wo[(size_t)(jt * 64 + r) * D_ + h * 64 + e];
    }
    __syncthreads();

    const int tj = (tid >> 4) << 2;
    const int td = (tid & 15) << 2;
    float acc[4][4];
#pragma unroll
    for (int i = 0; i < 4; i++)
#pragma unroll
        for (int j = 0; j < 4; j++) acc[i][j] = 0.f;

#pragma unroll 16
    for (int e = 0; e < 64; e++) {
        float wv[4], kvv[4];
#pragma unroll
        for (int i = 0; i < 4; i++) { wv[i] = Wos[tj + i][e]; kvv[i] = kvs[td + i][e]; }
#pragma unroll
        for (int i = 0; i < 4; i++)
#pragma unroll
            for (int j = 0; j < 4; j++)
                acc[i][j] = fmaf(wv[i], kvv[j], acc[i][j]);
    }

    float sc[4];
#pragma unroll
    for (int j = 0; j < 4; j++)
        sc[j] = 1.0f / fmaxf(sqrtf(g_qnorm[b * D_ + h * 64 + td + j]), 1e-12f);

    const size_t ob = ((size_t)b << 20) + (size_t)(jt * 64 + tj) * D_ + h * 64 + td;
#pragma unroll
    for (int i = 0; i < 4; i++) {
        uint32_t h01, l01, h23, l23;
        split_pack(acc[i][0] * sc[0], acc[i][1] * sc[1], h01, l01);
        split_pack(acc[i][2] * sc[2], acc[i][3] * sc[3], h23, l23);
        *(uint2*)(g_GThi + ob + (size_t)i * D_) = make_uint2(h01, h23);
        *(uint2*)(g_GTlo + ob + (size_t)i * D_) = make_uint2(l01, l23);
    }
}

// ---------------------------------------------------------------------------
extern "C" void kernel_launch(void* const* d_in, const int* in_sizes, int n_in,
                              void* d_out, int out_size)
{
    (void)in_sizes; (void)n_in; (void)out_size;
    const float* query = (const float*)d_in[0];
    const float* key   = (const float*)d_in[1];
    const float* value = (const float*)d_in[2];
    const int*   mask  = (const int*)d_in[3];   // bool materialized as int32
    const float* Wq = (const float*)d_in[4];
    const float* bq = (const float*)d_in[5];
    const float* Wk = (const float*)d_in[6];
    const float* bk = (const float*)d_in[7];
    const float* Wv = (const float*)d_in[8];
    const float* bv = (const float*)d_in[9];
    const float* Wo = (const float*)d_in[10];
    const float* bo = (const float*)d_in[11];
    float* out = (float*)d_out;

    float* Q = nullptr;
    cudaGetSymbolAddress((void**)&Q, g_Q);

    cudaFuncSetAttribute(gemm_qkv, cudaFuncAttributeMaxDynamicSharedMemorySize, GEMM_SMEM);
    cudaFuncSetAttribute(gemm_out, cudaFuncAttributeMaxDynamicSharedMemorySize, GEMM_SMEM);

    dim3 gblk(256);

    // launches 0..2 (keeps fused QKV gemm at capture index 3)
    split_w_kernel<<<dim3(1024, 3), 256>>>(Wq, Wk, Wv);
    zero_qnorm_kernel<<<(B_ * D_ + 255) / 256, 256>>>();
    zero_kv_kernel<<<(B_ * H_ * DH_ * DH_ + 255) / 256, 256>>>();

    gemm_qkv<<<dim3(D_ / 128, M_ / 128, 3), gblk, GEMM_SMEM>>>(
        query, key, value, bq, bk, bv, mask);

    qcolsumsq_kernel<<<dim3(4, 16, 8), 256>>>();
    kv_fused_kernel<<<dim3(B_ * H_, 8), 256>>>();
    gt_kernel<<<dim3(16, 16, 8), 256>>>(Wo);

    gemm_out<<<dim3(D_ / 128, M_ / 128), gblk, GEMM_SMEM>>>(Q, bo, out);
}